// round 2
// baseline (speedup 1.0000x reference)
#include <cuda_runtime.h>
#include <math.h>

// Problem constants (fixed by setup_inputs): N=100000, E=1600000, F_IN=256, F_OUT=40
#define N_MAX 100000
#define E_MAX 1600000
#define F_IN  256
#define F_OUT 40
#define F4    (F_OUT / 4)   // 10 float4 chunks per node row

// Scratch in __device__ globals (no allocation allowed in kernel_launch).
__device__ int   g_is64;
__device__ float g_deg [N_MAX];
__device__ float g_dinv[N_MAX];
__device__ float g_norm[E_MAX];
__device__ int   g_row [E_MAX];
__device__ int   g_col [E_MAX];
__device__ float g_bufA[(size_t)N_MAX * F_OUT];
__device__ float g_bufB[(size_t)N_MAX * F_OUT];

// ---------------------------------------------------------------------------
// 0) dtype detection: int64 edge_index has all probe values in [0,N);
//    int32 data reinterpreted as int64 yields values >= 2^32 (w.h.p.).
__global__ void k_detect(const void* __restrict__ ei_raw, int N) {
    if (blockIdx.x == 0 && threadIdx.x == 0) {
        const long long* p = (const long long*)ei_raw;
        int ok64 = 1;
        for (int i = 0; i < 64; i++) {
            long long v = p[i];
            if (v < 0 || v >= (long long)N) { ok64 = 0; break; }
        }
        g_is64 = ok64;
    }
}

__device__ __forceinline__ int load_idx(const void* ei, size_t pos, int is64, int N) {
    int v = is64 ? (int)((const long long*)ei)[pos]
                 : ((const int*)ei)[pos];
    // clamp: wrong dtype degrades to rel_err failure, never a crash
    v = v < 0 ? 0 : (v >= N ? N - 1 : v);
    return v;
}

// 1) degree init: self-loop weight 1 per node
__global__ void k_init_deg(int N) {
    int i = blockIdx.x * blockDim.x + threadIdx.x;
    if (i < N) g_deg[i] = 1.0f;
}

// 2) degree accumulate: deg[col[e]] += w[e]
__global__ void k_deg_accum(const void* __restrict__ ei,
                            const float* __restrict__ w, int E, int N) {
    int e = blockIdx.x * blockDim.x + threadIdx.x;
    if (e < E) {
        int is64 = g_is64;
        int c = load_idx(ei, (size_t)E + e, is64, N);
        atomicAdd(&g_deg[c], w[e]);
    }
}

// 3) dinv = rsqrt(deg)  (deg >= 1 always)
__global__ void k_dinv(int N) {
    int i = blockIdx.x * blockDim.x + threadIdx.x;
    if (i < N) g_dinv[i] = rsqrtf(g_deg[i]);
}

// 4) per-edge norm + int32 copies of row/col
__global__ void k_edge_norm(const void* __restrict__ ei,
                            const float* __restrict__ w, int E, int N) {
    int e = blockIdx.x * blockDim.x + threadIdx.x;
    if (e < E) {
        int is64 = g_is64;
        int r = load_idx(ei, (size_t)e,     is64, N);
        int c = load_idx(ei, (size_t)E + e, is64, N);
        g_row[e] = r;
        g_col[e] = c;
        g_norm[e] = g_dinv[r] * w[e] * g_dinv[c];
    }
}

// ---------------------------------------------------------------------------
// 5) GEMM: z = x @ W^T   (N x 256) @ (256 x 40) -> bufA
//    One thread per node, 40 fp32 accumulators, W staged in SMEM (40 KB).
//    W[j,k] LDS is the same address across the warp -> broadcast, free.
__global__ void k_gemm(const float* __restrict__ x,
                       const float* __restrict__ W, int N) {
    __shared__ float Ws[F_OUT * F_IN];
    for (int i = threadIdx.x; i < F_OUT * F_IN; i += blockDim.x)
        Ws[i] = W[i];
    __syncthreads();

    int n = blockIdx.x * blockDim.x + threadIdx.x;
    if (n >= N) return;

    float acc[F_OUT];
#pragma unroll
    for (int j = 0; j < F_OUT; j++) acc[j] = 0.0f;

    const float4* xr = (const float4*)(x + (size_t)n * F_IN);
#pragma unroll 2
    for (int k4 = 0; k4 < F_IN / 4; k4++) {
        float4 xv = xr[k4];
#pragma unroll
        for (int j = 0; j < F_OUT; j++) {
            float4 wv = *(const float4*)&Ws[j * F_IN + k4 * 4];
            acc[j] = fmaf(xv.x, wv.x,
                     fmaf(xv.y, wv.y,
                     fmaf(xv.z, wv.z,
                     fmaf(xv.w, wv.w, acc[j]))));
        }
    }

    float4* zr = (float4*)(g_bufA + (size_t)n * F_OUT);
#pragma unroll
    for (int c = 0; c < F4; c++)
        zr[c] = make_float4(acc[4*c+0], acc[4*c+1], acc[4*c+2], acc[4*c+3]);
}

// ---------------------------------------------------------------------------
// 6) self-loop term initializes the destination buffer:
//    dst[i,:] = dinv[i]^2 * src[i,:]
template <bool AtoB>
__global__ void k_selfloop(int N) {
    int t = blockIdx.x * blockDim.x + threadIdx.x;
    if (t >= N * F4) return;
    const float4* src = (const float4*)(AtoB ? g_bufA : g_bufB);
    float4*       dst = (float4*)(AtoB ? g_bufB : g_bufA);
    int i = t / F4;
    float d = g_dinv[i];
    float d2 = d * d;
    float4 v = src[t];
    dst[t] = make_float4(d2 * v.x, d2 * v.y, d2 * v.z, d2 * v.w);
}

// 7) edge scatter: dst[col,:] += norm[e] * src[row,:]
//    One thread per edge; 10 float4 gathers (L2-resident) + 40 fp32 atomics.
template <bool AtoB>
__global__ void k_scatter(int E) {
    int e = blockIdx.x * blockDim.x + threadIdx.x;
    if (e >= E) return;
    const float* srcf = AtoB ? g_bufA : g_bufB;
    float*       dstf = AtoB ? g_bufB : g_bufA;

    int r = g_row[e];
    int c = g_col[e];
    float nrm = g_norm[e];

    const float4* s = (const float4*)srcf + (size_t)r * F4;
    float*        d = dstf + (size_t)c * F_OUT;
#pragma unroll
    for (int ch = 0; ch < F4; ch++) {
        float4 v = s[ch];
        atomicAdd(d + ch * 4 + 0, nrm * v.x);
        atomicAdd(d + ch * 4 + 1, nrm * v.y);
        atomicAdd(d + ch * 4 + 2, nrm * v.z);
        atomicAdd(d + ch * 4 + 3, nrm * v.w);
    }
}

// ---------------------------------------------------------------------------
// 8) epilogue: out = log_softmax(relu(h + b))   h = bufA after hop 2
__global__ void k_final(const float* __restrict__ b,
                        float* __restrict__ out, int N) {
    int n = blockIdx.x * blockDim.x + threadIdx.x;
    if (n >= N) return;

    float v[F_OUT];
    const float4* h = (const float4*)g_bufA + (size_t)n * F4;
#pragma unroll
    for (int c = 0; c < F4; c++) {
        float4 t = h[c];
        v[4*c+0] = t.x; v[4*c+1] = t.y; v[4*c+2] = t.z; v[4*c+3] = t.w;
    }
#pragma unroll
    for (int j = 0; j < F_OUT; j++)
        v[j] = fmaxf(v[j] + __ldg(&b[j]), 0.0f);

    float m = -1e30f;
#pragma unroll
    for (int j = 0; j < F_OUT; j++) m = fmaxf(m, v[j]);
    float s = 0.0f;
#pragma unroll
    for (int j = 0; j < F_OUT; j++) s += expf(v[j] - m);
    float lse = m + logf(s);

    float4* o = (float4*)out + (size_t)n * F4;
#pragma unroll
    for (int c = 0; c < F4; c++)
        o[c] = make_float4(v[4*c+0] - lse, v[4*c+1] - lse,
                           v[4*c+2] - lse, v[4*c+3] - lse);
}

// ---------------------------------------------------------------------------
extern "C" void kernel_launch(void* const* d_in, const int* in_sizes, int n_in,
                              void* d_out, int out_size) {
    const float* x   = (const float*)d_in[0];
    const void*  ei  = d_in[1];
    const float* w   = (const float*)d_in[2];
    const float* W   = (const float*)d_in[3];
    const float* b   = (const float*)d_in[4];
    float*       out = (float*)d_out;

    int N = in_sizes[0] / F_IN;   // 100000
    int E = in_sizes[2];          // 1600000

    const int T = 256;
    int gN  = (N + T - 1) / T;
    int gE  = (E + T - 1) / T;
    int gNF = (N * F4 + T - 1) / T;

    // dtype probe + normalization precompute
    k_detect   <<<1, 32>>>(ei, N);
    k_init_deg <<<gN, T>>>(N);
    k_deg_accum<<<gE, T>>>(ei, w, E, N);
    k_dinv     <<<gN, T>>>(N);
    k_edge_norm<<<gE, T>>>(ei, w, E, N);

    // projection-first: z = x W^T  (40-wide from here on)
    k_gemm<<<gN, T>>>(x, W, N);

    // hop 1: bufB = P * bufA
    k_selfloop<true> <<<gNF, T>>>(N);
    k_scatter <true> <<<gE,  T>>>(E);

    // hop 2: bufA = P * bufB
    k_selfloop<false><<<gNF, T>>>(N);
    k_scatter <false><<<gE,  T>>>(E);

    // epilogue
    k_final<<<gN, T>>>(b, out, N);
}

// round 3
// speedup vs baseline: 4.6248x; 4.6248x over previous
#include <cuda_runtime.h>
#include <math.h>

// Problem constants: N=100000, E=1600000, F_IN=256, F_OUT=40
#define N_MAX 100000
#define E_MAX 1600000
#define F_IN  256
#define F_OUT 40
#define F4    (F_OUT / 4)   // 10 float4 chunks per node row
#define SCAN_BS 1024
#define SCAN_NB ((N_MAX + SCAN_BS - 1) / SCAN_BS)   // 98

// Scratch in __device__ globals (no allocation allowed in kernel_launch).
__device__ int    g_is64;
__device__ float  g_deg [N_MAX];
__device__ float  g_dinv[N_MAX];
__device__ int    g_rowi[E_MAX];       // decoded int32 row
__device__ int    g_coli[E_MAX];       // decoded int32 col
__device__ int    g_cnt [N_MAX];       // histogram of col
__device__ int    g_cur [N_MAX];       // bucket cursors
__device__ int    g_scan[N_MAX];       // per-block inclusive scan
__device__ int    g_ptr [N_MAX + 1];   // CSR offsets (by destination)
__device__ int    g_bsum[SCAN_NB];
__device__ int    g_boff[SCAN_NB];
__device__ int2   g_rec [E_MAX];       // sorted-by-dst: {src_row, bits(norm)}
__device__ float4 g_bufA[(size_t)N_MAX * F4];
__device__ float4 g_bufB[(size_t)N_MAX * F4];

// ---------------------------------------------------------------------------
// 0) dtype detection: int64 edge_index has all probe values in [0,N);
//    int32 reinterpreted as int64 yields values >= 2^32 (w.h.p.).
__global__ void k_detect(const void* __restrict__ ei_raw, int N) {
    if (blockIdx.x == 0 && threadIdx.x == 0) {
        const long long* p = (const long long*)ei_raw;
        int ok64 = 1;
        for (int i = 0; i < 64; i++) {
            long long v = p[i];
            if (v < 0 || v >= (long long)N) { ok64 = 0; break; }
        }
        g_is64 = ok64;
    }
}

__device__ __forceinline__ int load_idx(const void* ei, size_t pos, int is64, int N) {
    int v = is64 ? (int)((const long long*)ei)[pos]
                 : ((const int*)ei)[pos];
    v = v < 0 ? 0 : (v >= N ? N - 1 : v);   // clamp: never crash
    return v;
}

// 1) init: deg = 1 (self-loop), cnt = 0
__global__ void k_init(int N) {
    int i = blockIdx.x * blockDim.x + threadIdx.x;
    if (i < N) { g_deg[i] = 1.0f; g_cnt[i] = 0; }
}

// 2) decode indices once; accumulate degree + histogram
__global__ void k_prep_edges(const void* __restrict__ ei,
                             const float* __restrict__ w, int E, int N) {
    int e = blockIdx.x * blockDim.x + threadIdx.x;
    if (e < E) {
        int is64 = g_is64;
        int r = load_idx(ei, (size_t)e,     is64, N);
        int c = load_idx(ei, (size_t)E + e, is64, N);
        g_rowi[e] = r;
        g_coli[e] = c;
        atomicAdd(&g_deg[c], w[e]);
        atomicAdd(&g_cnt[c], 1);
    }
}

// 3) dinv = rsqrt(deg)
__global__ void k_dinv(int N) {
    int i = blockIdx.x * blockDim.x + threadIdx.x;
    if (i < N) g_dinv[i] = rsqrtf(g_deg[i]);
}

// 4a) per-block inclusive scan of cnt
__global__ void k_scanA(int N) {
    __shared__ int s[SCAN_BS];
    int i = blockIdx.x * SCAN_BS + threadIdx.x;
    int v = (i < N) ? g_cnt[i] : 0;
    s[threadIdx.x] = v;
    __syncthreads();
#pragma unroll
    for (int off = 1; off < SCAN_BS; off <<= 1) {
        int t = (threadIdx.x >= off) ? s[threadIdx.x - off] : 0;
        __syncthreads();
        s[threadIdx.x] += t;
        __syncthreads();
    }
    if (i < N) g_scan[i] = s[threadIdx.x];
    if (threadIdx.x == SCAN_BS - 1) g_bsum[blockIdx.x] = s[threadIdx.x];
}

// 4b) serial scan of block sums (98 values)
__global__ void k_scanB(int nb) {
    if (threadIdx.x == 0 && blockIdx.x == 0) {
        int run = 0;
        for (int b = 0; b < nb; b++) { g_boff[b] = run; run += g_bsum[b]; }
    }
}

// 4c) finalize exclusive ptr; zero cursors
__global__ void k_scanC(int N) {
    int i = blockIdx.x * blockDim.x + threadIdx.x;
    if (i < N) {
        g_ptr[i + 1] = g_scan[i] + g_boff[i / SCAN_BS];
        g_cur[i] = 0;
        if (i == 0) g_ptr[0] = 0;
    }
}

// 5) bucket fill: sorted-by-destination edge records {src, norm}
__global__ void k_fill(const float* __restrict__ w, int E) {
    int e = blockIdx.x * blockDim.x + threadIdx.x;
    if (e < E) {
        int r = g_rowi[e];
        int c = g_coli[e];
        float nrm = g_dinv[r] * w[e] * g_dinv[c];
        int pos = g_ptr[c] + atomicAdd(&g_cur[c], 1);
        g_rec[pos] = make_int2(r, __float_as_int(nrm));
    }
}

// ---------------------------------------------------------------------------
// 6) GEMM: z = x @ W^T  -> bufA.  W staged in SMEM (broadcast LDS).
__global__ void k_gemm(const float* __restrict__ x,
                       const float* __restrict__ W, int N) {
    __shared__ float Ws[F_OUT * F_IN];
    for (int i = threadIdx.x; i < F_OUT * F_IN; i += blockDim.x)
        Ws[i] = W[i];
    __syncthreads();

    int n = blockIdx.x * blockDim.x + threadIdx.x;
    if (n >= N) return;

    float acc[F_OUT];
#pragma unroll
    for (int j = 0; j < F_OUT; j++) acc[j] = 0.0f;

    const float4* xr = (const float4*)(x + (size_t)n * F_IN);
#pragma unroll 2
    for (int k4 = 0; k4 < F_IN / 4; k4++) {
        float4 xv = xr[k4];
#pragma unroll
        for (int j = 0; j < F_OUT; j++) {
            float4 wv = *(const float4*)&Ws[j * F_IN + k4 * 4];
            acc[j] = fmaf(xv.x, wv.x,
                     fmaf(xv.y, wv.y,
                     fmaf(xv.z, wv.z,
                     fmaf(xv.w, wv.w, acc[j]))));
        }
    }

    float4* zr = g_bufA + (size_t)n * F4;
#pragma unroll
    for (int c = 0; c < F4; c++)
        zr[c] = make_float4(acc[4*c+0], acc[4*c+1], acc[4*c+2], acc[4*c+3]);
}

// ---------------------------------------------------------------------------
// 7) pull hop: dst[i,:] = dinv[i]^2*src[i,:] + sum_{e: col=i} norm_e*src[row_e,:]
//    One thread per (node, float4 chunk). Atomic-free, L2-resident gathers.
template <bool AtoB>
__global__ void k_hop(int N) {
    int t = blockIdx.x * blockDim.x + threadIdx.x;
    if (t >= N * F4) return;
    const float4* __restrict__ src = AtoB ? g_bufA : g_bufB;
    float4*       __restrict__ dst = AtoB ? g_bufB : g_bufA;

    int node = t / F4;
    int ch   = t - node * F4;

    float d  = g_dinv[node];
    float d2 = d * d;
    float4 sv = src[(size_t)node * F4 + ch];
    float4 acc = make_float4(d2 * sv.x, d2 * sv.y, d2 * sv.z, d2 * sv.w);

    int beg = g_ptr[node];
    int end = g_ptr[node + 1];
    for (int e = beg; e < end; e++) {
        int2  rec = g_rec[e];
        float nrm = __int_as_float(rec.y);
        float4 v  = src[(size_t)rec.x * F4 + ch];
        acc.x = fmaf(nrm, v.x, acc.x);
        acc.y = fmaf(nrm, v.y, acc.y);
        acc.z = fmaf(nrm, v.z, acc.z);
        acc.w = fmaf(nrm, v.w, acc.w);
    }
    dst[t] = acc;
}

// ---------------------------------------------------------------------------
// 8) epilogue: out = log_softmax(relu(h + b))   h = bufA after hop 2
__global__ void k_final(const float* __restrict__ b,
                        float* __restrict__ out, int N) {
    int n = blockIdx.x * blockDim.x + threadIdx.x;
    if (n >= N) return;

    float v[F_OUT];
    const float4* h = g_bufA + (size_t)n * F4;
#pragma unroll
    for (int c = 0; c < F4; c++) {
        float4 t = h[c];
        v[4*c+0] = t.x; v[4*c+1] = t.y; v[4*c+2] = t.z; v[4*c+3] = t.w;
    }
#pragma unroll
    for (int j = 0; j < F_OUT; j++)
        v[j] = fmaxf(v[j] + __ldg(&b[j]), 0.0f);

    float m = -1e30f;
#pragma unroll
    for (int j = 0; j < F_OUT; j++) m = fmaxf(m, v[j]);
    float s = 0.0f;
#pragma unroll
    for (int j = 0; j < F_OUT; j++) s += expf(v[j] - m);
    float lse = m + logf(s);

    float4* o = (float4*)out + (size_t)n * F4;
#pragma unroll
    for (int c = 0; c < F4; c++)
        o[c] = make_float4(v[4*c+0] - lse, v[4*c+1] - lse,
                           v[4*c+2] - lse, v[4*c+3] - lse);
}

// ---------------------------------------------------------------------------
extern "C" void kernel_launch(void* const* d_in, const int* in_sizes, int n_in,
                              void* d_out, int out_size) {
    const float* x   = (const float*)d_in[0];
    const void*  ei  = d_in[1];
    const float* w   = (const float*)d_in[2];
    const float* W   = (const float*)d_in[3];
    const float* b   = (const float*)d_in[4];
    float*       out = (float*)d_out;

    int N = in_sizes[0] / F_IN;   // 100000
    int E = in_sizes[2];          // 1600000

    const int T = 256;
    int gN  = (N + T - 1) / T;
    int gE  = (E + T - 1) / T;
    int gNF = (N * F4 + T - 1) / T;
    int nb  = (N + SCAN_BS - 1) / SCAN_BS;

    // dtype probe + decode + degree + histogram
    k_detect    <<<1, 32>>>(ei, N);
    k_init      <<<gN, T>>>(N);
    k_prep_edges<<<gE, T>>>(ei, w, E, N);
    k_dinv      <<<gN, T>>>(N);

    // CSR build (counting sort by destination)
    k_scanA<<<nb, SCAN_BS>>>(N);
    k_scanB<<<1, 32>>>(nb);
    k_scanC<<<gN, T>>>(N);
    k_fill <<<gE, T>>>(w, E);

    // projection-first: z = x W^T  (40-wide from here on)
    k_gemm<<<gN, T>>>(x, W, N);

    // two atomic-free pull hops
    k_hop<true> <<<gNF, T>>>(N);
    k_hop<false><<<gNF, T>>>(N);

    // epilogue
    k_final<<<gN, T>>>(b, out, N);
}